// round 16
// baseline (speedup 1.0000x reference)
#include <cuda_runtime.h>
#include <cstdint>

#define BATCH 8
#define HS 256
#define WS 256
#define H 512
#define W 512
#define HW (H*W)
#define NITER 5

#define TILE 32
#define HALO 10                 // 2*NITER total dependency radius (mask)
#define S 52                    // TILE + 2*HALO
#define NCL 13                  // 52*64/256: cells per thread in bit/tile sweep
#define WLMAX 2048              // frontier cells inside conv domain (<= 40*40)

// V tile: halo 5 only -> rows/cols 5..46 of the 52x52 logical tile
#define VOFF 5
#define VS 42
#define VSX 48                  // padded stride

#define ENC  0x7FFFFFFF
// interior column masks for frontier words (mask update): cols 1..50
#define MASK_W0 0xFFFFFFFEu
#define MASK_W1 0x0007FFFFu

// k_compute tiling: 32x16 quads per CTA (2 quads/thread), 34x18 cell halo tile
#define QTX 32
#define QTY 16
#define CTX 34
#define CTY 18
#define CTN (CTX*CTY)           // 612

// ---------------- scratch (static device globals; no runtime allocation) ----------------
__device__ int    g_win[BATCH*HW];   // 0 = no winner; else ENC - source_index (atomicMax)
__device__ float2 g_d  [BATCH*HW];

// ---------------- 2x bilinear upsample of (src - base), scale, scatter winner ----------
// 2 horizontally-adjacent quads per thread (shared 3x4 cell window).
__global__ __launch_bounds__(256) void k_compute(const float2* __restrict__ src,
                                                 const float2* __restrict__ base) {
    __shared__ float2 ds[CTN];

    int b   = blockIdx.z;
    int qx0 = blockIdx.x * QTX;
    int qy0 = blockIdx.y * QTY;
    int tid = threadIdx.x;

    const float2* sb = src + (size_t)b * HS * WS;

    // load 34x18 cell tile of (src - base), edge-clamped
    for (int idx = tid; idx < CTN; idx += 256) {
        int row = idx / CTX, col = idx - row*CTX;
        int gy = min(max(qy0 - 1 + row, 0), HS-1);
        int gx = min(max(qx0 - 1 + col, 0), WS-1);
        int o = gy*WS + gx;
        float2 s = sb[o], bb = base[o];
        ds[idx] = make_float2(s.x - bb.x, s.y - bb.y);
    }
    __syncthreads();

    int txl = tid & 15, tyl = tid >> 4;
    int qpx = 2*txl;                     // local quad col of first quad
    int qy  = qy0 + tyl;

    // 3x4 cell window: rows tyl..tyl+2, cols qpx..qpx+3 (ds col 0 = qx0-1)
    float2 d0[4], d1[4], d2[4];
    #pragma unroll
    for (int e = 0; e < 4; e++) {
        d0[e] = ds[(tyl+0)*CTX + qpx + e];
        d1[e] = ds[(tyl+1)*CTX + qpx + e];
        d2[e] = ds[(tyl+2)*CTX + qpx + e];
    }

    // row interps: wy=0.75 for output row 2qy, wy=0.25 for row 2qy+1
    float2 a[4], cc[4];
    #pragma unroll
    for (int e = 0; e < 4; e++) {
        a[e]  = make_float2(d0[e].x*0.25f + d1[e].x*0.75f, d0[e].y*0.25f + d1[e].y*0.75f);
        cc[e] = make_float2(d1[e].x*0.75f + d2[e].x*0.25f, d1[e].y*0.75f + d2[e].y*0.25f);
    }

    const float sw = 0.5f * (float)W, sh = 0.5f * (float)H;
    // output pixels x0..x0+3 on rows y0, y0+1
    float2 oT[4], oB[4];
    #pragma unroll
    for (int k = 0; k < 2; k++) {        // quad k
        oT[2*k+0] = make_float2((a[k].x*0.25f  + a[k+1].x*0.75f) * sw,
                                (a[k].y*0.25f  + a[k+1].y*0.75f) * sh);
        oT[2*k+1] = make_float2((a[k+1].x*0.75f + a[k+2].x*0.25f) * sw,
                                (a[k+1].y*0.75f + a[k+2].y*0.25f) * sh);
        oB[2*k+0] = make_float2((cc[k].x*0.25f  + cc[k+1].x*0.75f) * sw,
                                (cc[k].y*0.25f  + cc[k+1].y*0.75f) * sh);
        oB[2*k+1] = make_float2((cc[k+1].x*0.75f + cc[k+2].x*0.25f) * sw,
                                (cc[k+1].y*0.75f + cc[k+2].y*0.25f) * sh);
    }

    int x0 = 2*(qx0 + qpx), y0 = 2*qy;
    size_t gbase = (size_t)b*HW;
    *(float4*)&g_d[gbase + (size_t)y0*W + x0]       = make_float4(oT[0].x, oT[0].y, oT[1].x, oT[1].y);
    *(float4*)&g_d[gbase + (size_t)y0*W + x0 + 2]   = make_float4(oT[2].x, oT[2].y, oT[3].x, oT[3].y);
    *(float4*)&g_d[gbase + (size_t)(y0+1)*W + x0]     = make_float4(oB[0].x, oB[0].y, oB[1].x, oB[1].y);
    *(float4*)&g_d[gbase + (size_t)(y0+1)*W + x0 + 2] = make_float4(oB[2].x, oB[2].y, oB[3].x, oB[3].y);

    // round-half-even (rintf), oob check, min source index via max encoding
    #define SCATTER(px, py, vv) do {                                               \
        float fx = rintf((float)(px) + (vv).x);                                    \
        float fy = rintf((float)(py) + (vv).y);                                    \
        if (fx >= 0.0f && fy >= 0.0f && fx <= (float)(W-1) && fy <= (float)(H-1)) {\
            int ti = (int)gbase + (int)fy * W + (int)fx;                           \
            atomicMax(&g_win[ti], ENC - ((py)*W + (px)));                          \
        }                                                                          \
    } while (0)
    #pragma unroll
    for (int e = 0; e < 4; e++) {
        SCATTER(x0+e, y0,   oT[e]);
        SCATTER(x0+e, y0+1, oB[e]);
    }
    #undef SCATTER
}

// ---------------- fused: winner gather + 5x dilation + 5x bit erosion + compose ---------
__global__ __launch_bounds__(256) void k_fused(const float* __restrict__ kw,
                                               const float2* __restrict__ tgt,
                                               float2* __restrict__ out) {
    __shared__ float2             smV[VS*VSX];  // V only on logical rows/cols 5..46
    __shared__ unsigned long long bm[2][S];     // ping-pong mask bit-planes
    __shared__ unsigned short     wl[WLMAX];    // frontier worklist (idx = r*64 + c)
    __shared__ int                wcnt[NITER];
    __shared__ float              skw[9];

    int b   = blockIdx.z;
    int tx0 = blockIdx.x * TILE - HALO;
    int ty0 = blockIdx.y * TILE - HALO;
    int tid = threadIdx.x;

    if (tid < 9) skw[tid] = kw[tid];
    if (tid < NITER) wcnt[tid] = 0;

    const int c    = tid & 63;
    const int r0   = tid >> 6;
    const int half = (tid >> 5) & 1;

    const int*    gwin = g_win + (size_t)b * HW;
    const float2* gd   = g_d   + (size_t)b * HW;

    // ---- phase A: issue ALL 13 winner loads into registers (MLP=13, before any ballot) ----
    int pw[NCL];
    #pragma unroll
    for (int j = 0; j < NCL; j++) {
        int r = r0 + 4*j;
        int px = tx0 + c, py = ty0 + r;
        bool in = (c < S) & (px >= 0) & (px < W) & (py >= 0) & (py < H);
        pw[j] = in ? gwin[py*W + px] : 0;
    }

    // ---- phase B: ballots -> mask bitwords ----
    #pragma unroll
    for (int j = 0; j < NCL; j++) {
        int r = r0 + 4*j;
        unsigned wball = __ballot_sync(0xffffffffu, pw[j] != 0);
        if ((tid & 31) == 0) ((unsigned*)&bm[0][r])[half] = wball;
    }

    // ---- phase C: gather winner displacement for set cells in V region [5,46]^2 ----
    const bool cInV = (c >= VOFF) & (c <= 46);
    #pragma unroll
    for (int j = 0; j < NCL; j++) {
        int r = r0 + 4*j;
        if (cInV & (r >= VOFF) & (r <= 46) & (pw[j] != 0)) {
            float2 d = gd[ENC - pw[j]];
            smV[(r-VOFF)*VSX + (c-VOFF)] = make_float2(-d.x, -d.y);
        }
    }
    __syncthreads();

    const bool act = tid < S*2;
    const int  wr  = tid >> 1, wk = tid & 1;
    int cur = 0;

    // ---- 5 dilation iterations ----
    for (int it = 0; it < NITER; it++) {
        if (act) {
            unsigned cw = ((unsigned*)&bm[cur][wr])[wk];
            unsigned up = (wr > 0)   ? ((unsigned*)&bm[cur][wr-1])[wk] : 0u;
            unsigned dn = (wr < S-1) ? ((unsigned*)&bm[cur][wr+1])[wk] : 0u;
            unsigned lw = (wk == 1)  ? ((unsigned*)&bm[cur][wr])[0]    : 0u;
            unsigned rw = (wk == 0)  ? ((unsigned*)&bm[cur][wr])[1]    : 0u;
            unsigned f = (up | dn | (cw << 1) | (lw >> 31) | (cw >> 1) | (rw << 31)) & ~cw;
            f &= wk ? MASK_W1 : MASK_W0;
            if (wr == 0 || wr == S-1) f = 0u;
            ((unsigned*)&bm[cur^1][wr])[wk] = cw | f;     // full-mask update (exactness cone)

            // conv domain at iteration k=it+1: rows/cols in [5+k, 46-k]
            unsigned fc = f & (wk ? ((1u << (14-it)) - 1u)      // hi word: cols 32..45-it
                                  : (0xFFFFFFFFu << (6+it)));   // lo word: cols 6+it..31
            if (wr < 6+it || wr > 45-it) fc = 0u;
            if (fc) {
                int ofs = atomicAdd(&wcnt[it], __popc(fc));
                int cellbase = wr*64 + wk*32;
                while (fc) {
                    int bit = __ffs(fc) - 1;
                    fc &= fc - 1;
                    wl[ofs++] = (unsigned short)(cellbase + bit);
                }
            }
        }
        __syncthreads();

        // conv at listed frontier cells (gates read OLD plane; V reads/writes in V tile)
        int n = wcnt[it];
        for (int k = tid; k < n; k += 256) {
            int idx = wl[k];
            int cc = idx & 63;
            int rr = idx >> 6;
            unsigned long long rm = bm[cur][rr-1], rc = bm[cur][rr], rp = bm[cur][rr+1];
            unsigned n0 = (unsigned)(rm >> (cc-1)) & 7u;
            unsigned n1 = (unsigned)(rc >> (cc-1)) & 7u;   // center bit = 0
            unsigned n2 = (unsigned)(rp >> (cc-1)) & 7u;
            int vidx = (rr-VOFF)*VSX + (cc-VOFF);
            float am = 0.0f, ax = 0.0f, ay = 0.0f;
            #define ACC(bit, kidx, off) \
                if (bit) { float kv = skw[kidx]; float2 v = smV[vidx + (off)]; \
                           am += kv; ax += kv * v.x; ay += kv * v.y; }
            ACC(n0 & 1u, 0, -VSX-1) ACC(n0 & 2u, 1, -VSX) ACC(n0 & 4u, 2, -VSX+1)
            ACC(n1 & 1u, 3, -1)                           ACC(n1 & 4u, 5, +1)
            ACC(n2 & 1u, 6,  VSX-1) ACC(n2 & 2u, 7,  VSX) ACC(n2 & 4u, 8,  VSX+1)
            #undef ACC
            smV[vidx] = make_float2(ax / am, ay / am);
        }
        __syncthreads();
        cur ^= 1;
    }

    // ---- 5 erosion iterations: 1 sync each ----
    for (int it = 0; it < NITER; it++) {
        if (act) {
            unsigned cw = ((unsigned*)&bm[cur][wr])[wk];
            unsigned up = (wr > 0)   ? ((unsigned*)&bm[cur][wr-1])[wk] : 0u;
            unsigned dn = (wr < S-1) ? ((unsigned*)&bm[cur][wr+1])[wk] : 0u;
            unsigned lw = (wk == 1)  ? ((unsigned*)&bm[cur][wr])[0]    : 0u;
            unsigned rw = (wk == 0)  ? ((unsigned*)&bm[cur][wr])[1]    : 0u;
            ((unsigned*)&bm[cur^1][wr])[wk] =
                cw & up & dn & ((cw << 1) | (lw >> 31)) & ((cw >> 1) | (rw << 31));
        }
        __syncthreads();
        cur ^= 1;
    }

    // ---- compose interior 32x32 (logical rows/cols 10..41 -> V tile 5..36) ----
    #pragma unroll
    for (int j = 0; j < (TILE*TILE)/256; j++) {
        int local = tid + j*256;
        int lyy = local >> 5, lxx = local & 31;
        int rr = lyy + HALO, cc = lxx + HALO;
        bool m = (bm[cur][rr] >> cc) & 1ull;
        float2 v = smV[(rr-VOFF)*VSX + (cc-VOFF)];
        int py = ty0 + rr, px = tx0 + cc;
        int g = py*W + px;
        float vx = m ? v.x * (2.0f / (float)W) : 4.0f;
        float vy = m ? v.y * (2.0f / (float)H) : 4.0f;
        float2 t2 = tgt[g];
        out[(size_t)b*HW + g] = make_float2(t2.x + vx, t2.y + vy);
    }
}

extern "C" void kernel_launch(void* const* d_in, const int* in_sizes, int n_in,
                              void* d_out, int out_size) {
    const float* src  = nullptr;   // 8*256*256*2  = 1048576
    const float* kw   = nullptr;   // 3*3          = 9
    const float* base = nullptr;   // 1*256*256*2  = 131072
    const float* tgt  = nullptr;   // 1*512*512*2  = 524288
    for (int j = 0; j < n_in; j++) {
        switch (in_sizes[j]) {
            case 1048576: src  = (const float*)d_in[j]; break;
            case 9:       kw   = (const float*)d_in[j]; break;
            case 131072:  base = (const float*)d_in[j]; break;
            case 524288:  tgt  = (const float*)d_in[j]; break;
            default: break;
        }
    }
    float* out = (float*)d_out;

    const int TB = 256;

    // reset winner array via driver memset (graph-capturable, no allocation)
    void* wp = nullptr;
    cudaGetSymbolAddress(&wp, g_win);
    cudaMemsetAsync(wp, 0, sizeof(int) * BATCH * HW);

    dim3 cgrid(WS/QTX, HS/QTY, BATCH);  // 8 x 16 x 8
    k_compute<<<cgrid, TB>>>((const float2*)src, (const float2*)base);

    dim3 grid(W/TILE, H/TILE, BATCH);   // 16 x 16 x 8
    k_fused<<<grid, TB>>>(kw, (const float2*)tgt, (float2*)out);
}

// round 17
// speedup vs baseline: 1.0993x; 1.0993x over previous
#include <cuda_runtime.h>
#include <cstdint>

#define BATCH 8
#define HS 256
#define WS 256
#define H 512
#define W 512
#define HW (H*W)
#define NITER 5

#define TILE 32
#define HALO 10                 // 2*NITER total dependency radius (mask)
#define S 52                    // TILE + 2*HALO
#define NCL 13                  // 52*64/256: cells per thread in bit/tile sweep
#define WLMAX 2048              // frontier cells inside conv domain (<= 40*40)

// V tile: halo 5 only -> rows/cols 5..46 of the 52x52 logical tile
#define VOFF 5
#define VS 42
#define VSX 48                  // padded stride

#define ENC  0x7FFFFFFF
// interior column masks for frontier words (mask update): cols 1..50
#define MASK_W0 0xFFFFFFFEu
#define MASK_W1 0x0007FFFFu

// k_compute tiling: 16x16 quads per CTA, 18x18 cell halo tile
#define QT 16
#define CT 18

// ---------------- scratch (static device globals; no runtime allocation) ----------------
__device__ int    g_win[BATCH*HW];   // 0 = no winner; else ENC - source_index (atomicMax)
__device__ float2 g_d  [BATCH*HW];

// ---------------- reset winner array: 512 CTAs, 4x int4 per thread, single wave --------
__global__ __launch_bounds__(256) void k_init() {
    int t = blockIdx.x * blockDim.x + threadIdx.x;   // 0 .. 131071
    int4* p = (int4*)g_win;                           // 524288 int4 total
    const int4 z = make_int4(0, 0, 0, 0);
    #pragma unroll
    for (int j = 0; j < 4; j++)
        p[t + j*131072] = z;
}

// ---------------- 2x bilinear upsample of (src - base), scale, scatter winner ----------
__global__ __launch_bounds__(256) void k_compute(const float2* __restrict__ src,
                                                 const float2* __restrict__ base) {
    __shared__ float2 ds[CT*CT];

    int b   = blockIdx.z;
    int qx0 = blockIdx.x * QT;
    int qy0 = blockIdx.y * QT;
    int tid = threadIdx.x;

    const float2* sb = src + (size_t)b * HS * WS;

    #pragma unroll
    for (int j = 0; j < 2; j++) {
        int idx = tid + j*256;
        if (idx < CT*CT) {
            int row = idx / CT, col = idx - row*CT;
            int gy = min(max(qy0 - 1 + row, 0), HS-1);
            int gx = min(max(qx0 - 1 + col, 0), WS-1);
            int o = gy*WS + gx;
            float2 s = sb[o], bb = base[o];
            ds[idx] = make_float2(s.x - bb.x, s.y - bb.y);
        }
    }
    __syncthreads();

    int tx = tid & 15, ty = tid >> 4;
    int qx = qx0 + tx, qy = qy0 + ty;

    float2 d00 = ds[(ty+0)*CT + tx+0], d01 = ds[(ty+0)*CT + tx+1], d02 = ds[(ty+0)*CT + tx+2];
    float2 d10 = ds[(ty+1)*CT + tx+0], d11 = ds[(ty+1)*CT + tx+1], d12 = ds[(ty+1)*CT + tx+2];
    float2 d20 = ds[(ty+2)*CT + tx+0], d21 = ds[(ty+2)*CT + tx+1], d22 = ds[(ty+2)*CT + tx+2];

    float2 a0 = make_float2(d00.x*0.25f + d10.x*0.75f, d00.y*0.25f + d10.y*0.75f);
    float2 a1 = make_float2(d01.x*0.25f + d11.x*0.75f, d01.y*0.25f + d11.y*0.75f);
    float2 a2 = make_float2(d02.x*0.25f + d12.x*0.75f, d02.y*0.25f + d12.y*0.75f);
    float2 c0 = make_float2(d10.x*0.75f + d20.x*0.25f, d10.y*0.75f + d20.y*0.25f);
    float2 c1 = make_float2(d11.x*0.75f + d21.x*0.25f, d11.y*0.75f + d21.y*0.25f);
    float2 c2 = make_float2(d12.x*0.75f + d22.x*0.25f, d12.y*0.75f + d22.y*0.25f);

    const float sw = 0.5f * (float)W, sh = 0.5f * (float)H;
    float2 o00 = make_float2((a0.x*0.25f + a1.x*0.75f) * sw, (a0.y*0.25f + a1.y*0.75f) * sh);
    float2 o10 = make_float2((a1.x*0.75f + a2.x*0.25f) * sw, (a1.y*0.75f + a2.y*0.25f) * sh);
    float2 o01 = make_float2((c0.x*0.25f + c1.x*0.75f) * sw, (c0.y*0.25f + c1.y*0.75f) * sh);
    float2 o11 = make_float2((c1.x*0.75f + c2.x*0.25f) * sw, (c1.y*0.75f + c2.y*0.25f) * sh);

    int x0 = 2*qx, y0 = 2*qy;
    size_t gbase = (size_t)b*HW;
    *(float4*)&g_d[gbase + (size_t)y0*W + x0]     = make_float4(o00.x, o00.y, o10.x, o10.y);
    *(float4*)&g_d[gbase + (size_t)(y0+1)*W + x0] = make_float4(o01.x, o01.y, o11.x, o11.y);

    // round-half-even (rintf), oob check, min source index via max encoding
    #define SCATTER(px, py, vv) do {                                               \
        float fx = rintf((float)(px) + (vv).x);                                    \
        float fy = rintf((float)(py) + (vv).y);                                    \
        if (fx >= 0.0f && fy >= 0.0f && fx <= (float)(W-1) && fy <= (float)(H-1)) {\
            int ti = (int)gbase + (int)fy * W + (int)fx;                           \
            atomicMax(&g_win[ti], ENC - ((py)*W + (px)));                          \
        }                                                                          \
    } while (0)
    SCATTER(x0,   y0,   o00);
    SCATTER(x0+1, y0,   o10);
    SCATTER(x0,   y0+1, o01);
    SCATTER(x0+1, y0+1, o11);
    #undef SCATTER
}

// ---------------- fused: winner gather + 5x dilation + 5x bit erosion + compose ---------
__global__ __launch_bounds__(256) void k_fused(const float* __restrict__ kw,
                                               const float2* __restrict__ tgt,
                                               float2* __restrict__ out) {
    __shared__ float2             smV[VS*VSX];  // V only on logical rows/cols 5..46
    __shared__ unsigned long long bm[2][S];     // ping-pong mask bit-planes
    __shared__ unsigned short     wl[WLMAX];    // frontier worklist (idx = r*64 + c)
    __shared__ int                wcnt[NITER];
    __shared__ float              skw[9];

    int b   = blockIdx.z;
    int tx0 = blockIdx.x * TILE - HALO;
    int ty0 = blockIdx.y * TILE - HALO;
    int tid = threadIdx.x;

    if (tid < 9) skw[tid] = kw[tid];
    if (tid < NITER) wcnt[tid] = 0;

    const int c    = tid & 63;
    const int r0   = tid >> 6;
    const int half = (tid >> 5) & 1;

    const int*    gwin = g_win + (size_t)b * HW;
    const float2* gd   = g_d   + (size_t)b * HW;

    // ---- phase A: issue ALL 13 winner loads into registers (MLP=13, before any ballot) ----
    int pw[NCL];
    #pragma unroll
    for (int j = 0; j < NCL; j++) {
        int r = r0 + 4*j;
        int px = tx0 + c, py = ty0 + r;
        bool in = (c < S) & (px >= 0) & (px < W) & (py >= 0) & (py < H);
        pw[j] = in ? gwin[py*W + px] : 0;
    }

    // ---- phase B: ballots -> mask bitwords ----
    #pragma unroll
    for (int j = 0; j < NCL; j++) {
        int r = r0 + 4*j;
        unsigned wball = __ballot_sync(0xffffffffu, pw[j] != 0);
        if ((tid & 31) == 0) ((unsigned*)&bm[0][r])[half] = wball;
    }

    // ---- phase C: gather winner displacement for set cells in V region [5,46]^2 ----
    // (no convergent ops in this loop -> ptxas can pipeline the dependent gathers;
    //  V at mask-unset cells is NEVER read, so no zero-fill is needed.)
    const bool cInV = (c >= VOFF) & (c <= 46);
    #pragma unroll
    for (int j = 0; j < NCL; j++) {
        int r = r0 + 4*j;
        if (cInV & (r >= VOFF) & (r <= 46) & (pw[j] != 0)) {
            float2 d = gd[ENC - pw[j]];
            smV[(r-VOFF)*VSX + (c-VOFF)] = make_float2(-d.x, -d.y);
        }
    }
    __syncthreads();

    const bool act = tid < S*2;
    const int  wr  = tid >> 1, wk = tid & 1;
    int cur = 0;

    // ---- 5 dilation iterations ----
    for (int it = 0; it < NITER; it++) {
        if (act) {
            unsigned cw = ((unsigned*)&bm[cur][wr])[wk];
            unsigned up = (wr > 0)   ? ((unsigned*)&bm[cur][wr-1])[wk] : 0u;
            unsigned dn = (wr < S-1) ? ((unsigned*)&bm[cur][wr+1])[wk] : 0u;
            unsigned lw = (wk == 1)  ? ((unsigned*)&bm[cur][wr])[0]    : 0u;
            unsigned rw = (wk == 0)  ? ((unsigned*)&bm[cur][wr])[1]    : 0u;
            unsigned f = (up | dn | (cw << 1) | (lw >> 31) | (cw >> 1) | (rw << 31)) & ~cw;
            f &= wk ? MASK_W1 : MASK_W0;
            if (wr == 0 || wr == S-1) f = 0u;
            ((unsigned*)&bm[cur^1][wr])[wk] = cw | f;     // full-mask update (exactness cone)

            // conv domain at iteration k=it+1: rows/cols in [5+k, 46-k]
            unsigned fc = f & (wk ? ((1u << (14-it)) - 1u)      // hi word: cols 32..45-it
                                  : (0xFFFFFFFFu << (6+it)));   // lo word: cols 6+it..31
            if (wr < 6+it || wr > 45-it) fc = 0u;
            if (fc) {
                int ofs = atomicAdd(&wcnt[it], __popc(fc));
                int cellbase = wr*64 + wk*32;
                while (fc) {
                    int bit = __ffs(fc) - 1;
                    fc &= fc - 1;
                    wl[ofs++] = (unsigned short)(cellbase + bit);
                }
            }
        }
        __syncthreads();

        // conv at listed frontier cells (gates read OLD plane; V reads/writes in V tile)
        int n = wcnt[it];
        for (int k = tid; k < n; k += 256) {
            int idx = wl[k];
            int cc = idx & 63;
            int rr = idx >> 6;
            unsigned long long rm = bm[cur][rr-1], rc = bm[cur][rr], rp = bm[cur][rr+1];
            unsigned n0 = (unsigned)(rm >> (cc-1)) & 7u;
            unsigned n1 = (unsigned)(rc >> (cc-1)) & 7u;   // center bit = 0
            unsigned n2 = (unsigned)(rp >> (cc-1)) & 7u;
            int vidx = (rr-VOFF)*VSX + (cc-VOFF);
            float am = 0.0f, ax = 0.0f, ay = 0.0f;
            #define ACC(bit, kidx, off) \
                if (bit) { float kv = skw[kidx]; float2 v = smV[vidx + (off)]; \
                           am += kv; ax += kv * v.x; ay += kv * v.y; }
            ACC(n0 & 1u, 0, -VSX-1) ACC(n0 & 2u, 1, -VSX) ACC(n0 & 4u, 2, -VSX+1)
            ACC(n1 & 1u, 3, -1)                           ACC(n1 & 4u, 5, +1)
            ACC(n2 & 1u, 6,  VSX-1) ACC(n2 & 2u, 7,  VSX) ACC(n2 & 4u, 8,  VSX+1)
            #undef ACC
            smV[vidx] = make_float2(ax / am, ay / am);
        }
        __syncthreads();
        cur ^= 1;
    }

    // ---- 5 erosion iterations: 1 sync each ----
    for (int it = 0; it < NITER; it++) {
        if (act) {
            unsigned cw = ((unsigned*)&bm[cur][wr])[wk];
            unsigned up = (wr > 0)   ? ((unsigned*)&bm[cur][wr-1])[wk] : 0u;
            unsigned dn = (wr < S-1) ? ((unsigned*)&bm[cur][wr+1])[wk] : 0u;
            unsigned lw = (wk == 1)  ? ((unsigned*)&bm[cur][wr])[0]    : 0u;
            unsigned rw = (wk == 0)  ? ((unsigned*)&bm[cur][wr])[1]    : 0u;
            ((unsigned*)&bm[cur^1][wr])[wk] =
                cw & up & dn & ((cw << 1) | (lw >> 31)) & ((cw >> 1) | (rw << 31));
        }
        __syncthreads();
        cur ^= 1;
    }

    // ---- compose interior 32x32 (logical rows/cols 10..41 -> V tile 5..36) ----
    #pragma unroll
    for (int j = 0; j < (TILE*TILE)/256; j++) {
        int local = tid + j*256;
        int lyy = local >> 5, lxx = local & 31;
        int rr = lyy + HALO, cc = lxx + HALO;
        bool m = (bm[cur][rr] >> cc) & 1ull;
        float2 v = smV[(rr-VOFF)*VSX + (cc-VOFF)];
        int py = ty0 + rr, px = tx0 + cc;
        int g = py*W + px;
        float vx = m ? v.x * (2.0f / (float)W) : 4.0f;
        float vy = m ? v.y * (2.0f / (float)H) : 4.0f;
        float2 t2 = tgt[g];
        out[(size_t)b*HW + g] = make_float2(t2.x + vx, t2.y + vy);
    }
}

extern "C" void kernel_launch(void* const* d_in, const int* in_sizes, int n_in,
                              void* d_out, int out_size) {
    const float* src  = nullptr;   // 8*256*256*2  = 1048576
    const float* kw   = nullptr;   // 3*3          = 9
    const float* base = nullptr;   // 1*256*256*2  = 131072
    const float* tgt  = nullptr;   // 1*512*512*2  = 524288
    for (int j = 0; j < n_in; j++) {
        switch (in_sizes[j]) {
            case 1048576: src  = (const float*)d_in[j]; break;
            case 9:       kw   = (const float*)d_in[j]; break;
            case 131072:  base = (const float*)d_in[j]; break;
            case 524288:  tgt  = (const float*)d_in[j]; break;
            default: break;
        }
    }
    float* out = (float*)d_out;

    const int TB = 256;

    k_init<<<512, TB>>>();
    dim3 cgrid(WS/QT, HS/QT, BATCH);    // 16 x 16 x 8
    k_compute<<<cgrid, TB>>>((const float2*)src, (const float2*)base);

    dim3 grid(W/TILE, H/TILE, BATCH);   // 16 x 16 x 8
    k_fused<<<grid, TB>>>(kw, (const float2*)tgt, (float2*)out);
}